// round 1
// baseline (speedup 1.0000x reference)
#include <cuda_runtime.h>
#include <cuda_bf16.h>
#include <cstdint>

#define NUM_KNOTS 30
#define NI (NUM_KNOTS - 1)   // 29 intervals
#define PCHIP_EPS 1e-12f

// Per-interval cubic coefficients in local coordinate t in [0,1]:
//   p(t) = c0 + c1*t + c2*t^2 + c3*t^3
// Layout: g_coef[comp*NI + i]
__device__ float g_coef[4 * NI];
__device__ float g_params[3];   // k0, kK, scale = (K-1)/(kK-k0)

// ---------------------------------------------------------------------------
// Prep kernel: 1 thread. Reproduces the reference _pchip_slopes math in fp32
// and folds (y0, h*d0, y1, h*d1) into the t-polynomial coefficients.
// ---------------------------------------------------------------------------
__global__ void pchip_prep_kernel(const float* __restrict__ knots,
                                  const float* __restrict__ coeffs) {
    if (threadIdx.x != 0 || blockIdx.x != 0) return;

    float h[NI], delta[NI], d[NUM_KNOTS];
    #pragma unroll 1
    for (int i = 0; i < NI; i++) {
        h[i] = knots[i + 1] - knots[i];
        delta[i] = (coeffs[i + 1] - coeffs[i]) / (h[i] + PCHIP_EPS);
    }
    // interior slopes (weighted harmonic mean, zero at sign change)
    #pragma unroll 1
    for (int i = 1; i < NUM_KNOTS - 1; i++) {
        float hkm1 = h[i - 1], hk = h[i];
        float w1 = 2.0f * hk + hkm1;
        float w2 = hk + 2.0f * hkm1;
        bool same_sign = (delta[i - 1] * delta[i]) > 0.0f;
        float di = (w1 + w2) / (w1 / (delta[i - 1] + PCHIP_EPS) +
                                w2 / (delta[i]     + PCHIP_EPS));
        d[i] = same_sign ? di : 0.0f;
    }
    // endpoint slopes + limiter (order matters: zero-check, then 3x clamp)
    {
        float d0 = ((2.0f * h[0] + h[1]) * delta[0] - h[0] * delta[1]) /
                   (h[0] + h[1] + PCHIP_EPS);
        if (d0 * delta[0] <= 0.0f) d0 = 0.0f;
        if (fabsf(d0) > 3.0f * fabsf(delta[0])) d0 = 3.0f * delta[0];
        d[0] = d0;

        float dN = ((2.0f * h[NI - 1] + h[NI - 2]) * delta[NI - 1] -
                    h[NI - 1] * delta[NI - 2]) /
                   (h[NI - 1] + h[NI - 2] + PCHIP_EPS);
        if (dN * delta[NI - 1] <= 0.0f) dN = 0.0f;
        if (fabsf(dN) > 3.0f * fabsf(delta[NI - 1])) dN = 3.0f * delta[NI - 1];
        d[NUM_KNOTS - 1] = dN;
    }
    // Hermite -> t-polynomial per interval
    #pragma unroll 1
    for (int i = 0; i < NI; i++) {
        float y0 = coeffs[i], y1 = coeffs[i + 1];
        float hd0 = h[i] * d[i];
        float hd1 = h[i] * d[i + 1];
        g_coef[0 * NI + i] = y0;
        g_coef[1 * NI + i] = hd0;
        g_coef[2 * NI + i] = -3.0f * y0 - 2.0f * hd0 + 3.0f * y1 - hd1;
        g_coef[3 * NI + i] =  2.0f * y0 +        hd0 - 2.0f * y1 + hd1;
    }
    float k0 = knots[0];
    float kK = knots[NUM_KNOTS - 1];
    g_params[0] = k0;
    g_params[1] = kK;
    g_params[2] = (float)(NUM_KNOTS - 1) / (kK - k0);
}

// ---------------------------------------------------------------------------
// Streaming eval kernel. Coefficient table replicated 32x in shared memory
// (one copy per bank) -> the per-element random-index gather is always
// bank-conflict-free (bank == lane).
// Shared layout word index: comp*(NI*32) + idx*32 + lane.  NI*32 = 928 (mult
// of 32), so every component plane starts bank-aligned.
// ---------------------------------------------------------------------------
__device__ __forceinline__ float eval_one(float xv, float k0, float kK,
                                          float scale, const float* __restrict__ tl) {
    float xc = fminf(fmaxf(xv, k0), kK);
    float u = (xc - k0) * scale;        // in [0, 29]
    int idx = (int)u;                   // trunc == floor (u >= 0)
    idx = min(idx, NI - 1);
    float t = u - (float)idx;
    int o = idx * 32;
    float c0 = tl[o];
    float c1 = tl[o + 1 * NI * 32];
    float c2 = tl[o + 2 * NI * 32];
    float c3 = tl[o + 3 * NI * 32];
    return fmaf(fmaf(fmaf(c3, t, c2), t, c1), t, c0);
}

__global__ void __launch_bounds__(256)
spline_eval_kernel(const float4* __restrict__ x4, float4* __restrict__ out4,
                   int n4, int n, const float* __restrict__ x,
                   float* __restrict__ out) {
    __shared__ float tbl[4 * NI * 32];   // 14848 bytes

    // replicate table: each source value into all 32 banks
    for (int i = threadIdx.x; i < 4 * NI; i += blockDim.x) {
        float v = g_coef[i];
        #pragma unroll
        for (int r = 0; r < 32; r++) tbl[i * 32 + r] = v;
    }
    __syncthreads();

    const float k0 = g_params[0];
    const float kK = g_params[1];
    const float scale = g_params[2];
    const float* tl = tbl + (threadIdx.x & 31);

    int stride = gridDim.x * blockDim.x;
    int gid = blockIdx.x * blockDim.x + threadIdx.x;

    for (int i = gid; i < n4; i += stride) {
        float4 v = __ldcs(&x4[i]);
        float4 r;
        r.x = eval_one(v.x, k0, kK, scale, tl);
        r.y = eval_one(v.y, k0, kK, scale, tl);
        r.z = eval_one(v.z, k0, kK, scale, tl);
        r.w = eval_one(v.w, k0, kK, scale, tl);
        __stcs(&out4[i], r);
    }

    // scalar tail (n not multiple of 4)
    int tail_start = n4 * 4;
    for (int i = tail_start + gid; i < n; i += stride) {
        out[i] = eval_one(__ldcs(&x[i]), k0, kK, scale, tl);
    }
}

// ---------------------------------------------------------------------------
extern "C" void kernel_launch(void* const* d_in, const int* in_sizes, int n_in,
                              void* d_out, int out_size) {
    const float* x      = (const float*)d_in[0];
    const float* knots  = (const float*)d_in[1];
    const float* coeffs = (const float*)d_in[2];
    float* out = (float*)d_out;

    int n = out_size;
    int n4 = n / 4;

    pchip_prep_kernel<<<1, 1>>>(knots, coeffs);

    const int threads = 256;
    int blocks = 148 * 16;  // grid-stride; amortizes table replication
    int maxb = (n4 + threads - 1) / threads;
    if (maxb < 1) maxb = 1;
    if (blocks > maxb) blocks = maxb;

    spline_eval_kernel<<<blocks, threads>>>((const float4*)x, (float4*)out,
                                            n4, n, x, out);
}

// round 2
// speedup vs baseline: 1.2151x; 1.2151x over previous
#include <cuda_runtime.h>
#include <cuda_bf16.h>
#include <cstdint>

#define NUM_KNOTS 30
#define NI (NUM_KNOTS - 1)   // 29 intervals
#define PCHIP_EPS 1e-12f
#define REP 8                // table replication factor (8 copies -> conflict-free LDS.128)

// ---------------------------------------------------------------------------
// Fused kernel:
//   1. Warp 0 computes PCHIP slopes + per-interval cubic coefficients
//      (p(t) = c0 + c1 t + c2 t^2 + c3 t^3, t in [0,1]) warp-parallel via
//      shuffles, and writes an 8-way bank-replicated float4 table to smem.
//   2. All threads stream-evaluate with one LDS.128 per element.
//
// LDS.128 conflict analysis: lane L reads tbl[idx_L*8 + (L&7)].
// Word address = idx_L*32 + (L&7)*4 + w  ->  bank = 4*(L&7)+w (mod 32),
// independent of idx. Each 8-lane phase covers all 32 banks exactly once ->
// always the 4-wavefront (512B) minimum, regardless of the random idx.
// ---------------------------------------------------------------------------

__device__ __forceinline__ float eval_one(float xv, float k0, float kK,
                                          float scale,
                                          const float4* __restrict__ tl) {
    float xc = fminf(fmaxf(xv, k0), kK);
    float u = (xc - k0) * scale;          // in [0, NI]
    int idx = (int)u;                     // trunc == floor (u >= 0)
    idx = min(idx, NI - 1);
    float t = u - (float)idx;
    float4 c = tl[idx * REP];             // one LDS.128
    return fmaf(fmaf(fmaf(c.w, t, c.z), t, c.y), t, c.x);
}

__global__ void __launch_bounds__(256)
spline_fused_kernel(const float4* __restrict__ x4, float4* __restrict__ out4,
                    int n4, int n, const float* __restrict__ x,
                    float* __restrict__ out,
                    const float* __restrict__ knots,
                    const float* __restrict__ coeffs) {
    __shared__ float4 tbl[NI * REP];      // 3712 bytes
    __shared__ float s_par[3];            // k0, kK, scale

    const int tid = threadIdx.x;

    // ---- warp-parallel PCHIP prep (warp 0 only) ----
    if (tid < 32) {
        const unsigned FULL = 0xFFFFFFFFu;
        const int lane = tid;

        float k_i = (lane < NUM_KNOTS) ? knots[lane]  : 0.0f;
        float c_i = (lane < NUM_KNOTS) ? coeffs[lane] : 0.0f;
        float k_ip1 = __shfl_down_sync(FULL, k_i, 1);
        float c_ip1 = __shfl_down_sync(FULL, c_i, 1);

        float h = 0.0f, delta = 0.0f;
        if (lane < NI) {
            h = k_ip1 - k_i;
            delta = (c_ip1 - c_i) / (h + PCHIP_EPS);
        }
        float h_m1     = __shfl_up_sync(FULL, h, 1);
        float delta_m1 = __shfl_up_sync(FULL, delta, 1);
        float h_p1     = __shfl_down_sync(FULL, h, 1);
        float delta_p1 = __shfl_down_sync(FULL, delta, 1);

        float d = 0.0f;
        if (lane >= 1 && lane <= NI - 1) {
            // interior knot slope (weighted harmonic mean, 0 at sign change)
            float w1 = 2.0f * h + h_m1;
            float w2 = h + 2.0f * h_m1;
            float di = (w1 + w2) / (w1 / (delta_m1 + PCHIP_EPS) +
                                    w2 / (delta + PCHIP_EPS));
            d = (delta_m1 * delta > 0.0f) ? di : 0.0f;
        }
        if (lane == 0) {
            // left endpoint + limiter (zero-check first, then 3x clamp)
            float d0 = ((2.0f * h + h_p1) * delta - h * delta_p1) /
                       (h + h_p1 + PCHIP_EPS);
            if (d0 * delta <= 0.0f) d0 = 0.0f;
            else if (fabsf(d0) > 3.0f * fabsf(delta)) d0 = 3.0f * delta;
            d = d0;
        }
        float dN = 0.0f;
        if (lane == NI - 1) {
            // right endpoint computed on lane 28 (has h28, h27, delta28, delta27)
            dN = ((2.0f * h + h_m1) * delta - h * delta_m1) /
                 (h + h_m1 + PCHIP_EPS);
            if (dN * delta <= 0.0f) dN = 0.0f;
            else if (fabsf(dN) > 3.0f * fabsf(delta)) dN = 3.0f * delta;
        }
        float d_p1 = __shfl_down_sync(FULL, d, 1);   // d_{i+1}
        if (lane == NI - 1) d_p1 = dN;

        if (lane < NI) {
            float y0 = c_i, y1 = c_ip1;
            float hd0 = h * d;
            float hd1 = h * d_p1;
            float4 c;
            c.x = y0;
            c.y = hd0;
            c.z = -3.0f * y0 - 2.0f * hd0 + 3.0f * y1 - hd1;
            c.w =  2.0f * y0 +        hd0 - 2.0f * y1 + hd1;
            #pragma unroll
            for (int r = 0; r < REP; r++) tbl[lane * REP + r] = c;
        }
        if (lane == 0) {
            float k0 = knots[0];
            float kK = knots[NUM_KNOTS - 1];
            s_par[0] = k0;
            s_par[1] = kK;
            s_par[2] = (float)NI / (kK - k0);
        }
    }
    __syncthreads();

    const float k0 = s_par[0];
    const float kK = s_par[1];
    const float scale = s_par[2];
    const float4* tl = tbl + (tid & (REP - 1));

    int stride = gridDim.x * blockDim.x;
    int gid = blockIdx.x * blockDim.x + tid;

    for (int i = gid; i < n4; i += stride) {
        float4 v = __ldcs(&x4[i]);
        float4 r;
        r.x = eval_one(v.x, k0, kK, scale, tl);
        r.y = eval_one(v.y, k0, kK, scale, tl);
        r.z = eval_one(v.z, k0, kK, scale, tl);
        r.w = eval_one(v.w, k0, kK, scale, tl);
        __stcs(&out4[i], r);
    }

    // scalar tail (n not multiple of 4)
    int tail_start = n4 * 4;
    for (int i = tail_start + gid; i < n; i += stride) {
        out[i] = eval_one(__ldcs(&x[i]), k0, kK, scale, tl);
    }
}

// ---------------------------------------------------------------------------
extern "C" void kernel_launch(void* const* d_in, const int* in_sizes, int n_in,
                              void* d_out, int out_size) {
    const float* x      = (const float*)d_in[0];
    const float* knots  = (const float*)d_in[1];
    const float* coeffs = (const float*)d_in[2];
    float* out = (float*)d_out;

    int n = out_size;
    int n4 = n / 4;

    const int threads = 256;
    int blocks = 148 * 8;   // one full wave at 8 blocks/SM (2048 thr, 32 regs)
    int maxb = (n4 + threads - 1) / threads;
    if (maxb < 1) maxb = 1;
    if (blocks > maxb) blocks = maxb;

    spline_fused_kernel<<<blocks, threads>>>((const float4*)x, (float4*)out,
                                             n4, n, x, out, knots, coeffs);
}